// round 6
// baseline (speedup 1.0000x reference)
#include <cuda_runtime.h>
#include <cstdint>

#define BB 32
#define QQ 900
#define CCLS 91
#define TT 30
#define BIGV 1e9f
#define RPB 8
#define PBLK ((BB * QQ) / RPB)        // 3600 blocks in pseudo+fill
#define F4_PER_BLK 1800               // 3600*1800*4 floats = 25.92M = BB*QQ*QQ
#define NCH 8                         // row chunks per batch in sparse kernel
#define RCH ((QQ + NCH - 1) / NCH)    // 113

// per-row packed pseudo info: keep ? label : -1
__device__ int g_lk[BB * QQ];

// ---------------------------------------------------------------------------
// Kernel 1: warp-per-row pseudo labels + mask, FUSED with the BIG fill of the
// whole cost matrix (plain coalesced STG.128 — output fits in L2).
// Mask GIoU path uses exact IEEE op order (__f*_rn, no FMA contraction):
// a mask flip swaps ~O(10) values for 1e9 across a whole output column.
// ---------------------------------------------------------------------------
__global__ void __launch_bounds__(256)
pseudo_fill_kernel(const float* __restrict__ logits_base,
                   const float4* __restrict__ boxes_base,
                   const float4* __restrict__ targets,
                   float* __restrict__ out,        // cost matrix base
                   float* __restrict__ out_mask, int write_mask)
{
    // ---- BIG fill: this block's contiguous 28.8 KB slice ----
    {
        float4* o4 = (float4*)out + (size_t)blockIdx.x * F4_PER_BLK;
        const float4 big4 = make_float4(BIGV, BIGV, BIGV, BIGV);
#pragma unroll
        for (int t = threadIdx.x; t < F4_PER_BLK; t += 256)
            o4[t] = big4;
    }

    // ---- pseudo labels + mask (one warp per base row) ----
    int warp = (blockIdx.x * blockDim.x + threadIdx.x) >> 5;
    int lane = threadIdx.x & 31;
    int b = warp / QQ;

    // warp argmax over 91 logits (first-occurrence tie-break)
    const float* row = logits_base + (size_t)warp * CCLS;
    float best = -3.4e38f;
    int bi = 0;
    for (int c = lane; c < CCLS; c += 32) {
        float x = row[c];
        if (x > best) { best = x; bi = c; }
    }
#pragma unroll
    for (int off = 16; off > 0; off >>= 1) {
        float ov = __shfl_down_sync(0xFFFFFFFFu, best, off);
        int   oi = __shfl_down_sync(0xFFFFFFFFu, bi, off);
        if (ov > best || (ov == best && oi < bi)) { best = ov; bi = oi; }
    }
    best = __shfl_sync(0xFFFFFFFFu, best, 0);
    bi   = __shfl_sync(0xFFFFFFFFu, bi, 0);
    int keep = (best > 0.0f);                 // sigmoid(best) > 0.5

    float4 bb = boxes_base[warp];
    float bx0 = __fsub_rn(bb.x, __fmul_rn(0.5f, bb.z));
    float by0 = __fsub_rn(bb.y, __fmul_rn(0.5f, bb.w));
    float bx1 = __fadd_rn(bb.x, __fmul_rn(0.5f, bb.z));
    float by1 = __fadd_rn(bb.y, __fmul_rn(0.5f, bb.w));
    float barea = __fmul_rn(__fsub_rn(bx1, bx0), __fsub_rn(by1, by0));

    int bad = 0;
    if (lane < TT) {
        float4 tb = targets[b * TT + lane];
        float tx0 = __fsub_rn(tb.x, __fmul_rn(0.5f, tb.z));
        float ty0 = __fsub_rn(tb.y, __fmul_rn(0.5f, tb.w));
        float tx1 = __fadd_rn(tb.x, __fmul_rn(0.5f, tb.z));
        float ty1 = __fadd_rn(tb.y, __fmul_rn(0.5f, tb.w));
        float tarea = __fmul_rn(__fsub_rn(tx1, tx0), __fsub_rn(ty1, ty0));

        float lx = fmaxf(bx0, tx0), ly = fmaxf(by0, ty0);
        float rx = fminf(bx1, tx1), ry = fminf(by1, ty1);
        float w = fmaxf(__fsub_rn(rx, lx), 0.0f);
        float h = fmaxf(__fsub_rn(ry, ly), 0.0f);
        float inter = __fmul_rn(w, h);
        float uni = __fsub_rn(__fadd_rn(barea, tarea), inter);
        float iou = __fdiv_rn(inter, uni);

        float clx = fminf(bx0, tx0), cly = fminf(by0, ty0);
        float crx = fmaxf(bx1, tx1), cry = fmaxf(by1, ty1);
        float cw = fmaxf(__fsub_rn(crx, clx), 0.0f);
        float ch = fmaxf(__fsub_rn(cry, cly), 0.0f);
        float ac = __fmul_rn(cw, ch);
        float g = __fsub_rn(iou, __fdiv_rn(__fsub_rn(ac, uni), ac));
        bad = !(-g > -0.1f);
    }
    keep = keep && (__ballot_sync(0xFFFFFFFFu, bad) == 0u);

    if (lane == 0) {
        g_lk[warp] = keep ? bi : -1;
        if (write_mask) out_mask[warp] = keep ? 1.0f : 0.0f;
    }
}

// ---------------------------------------------------------------------------
// Kernel 2: sparse survivor columns. Grid (NCH, BB): block owns 113 rows of
// one batch. Block-local compaction of the batch's survivor list (cheap:
// 256 blocks total), then thread-per-row loop over survivors (broadcast
// loads), scattered 4B stores overwrite BIG at [row, j].
// ---------------------------------------------------------------------------
__global__ void __launch_bounds__(128)
sparse_kernel(const float4* __restrict__ pred_boxes,
              const float*  __restrict__ pred_logits,
              const float4* __restrict__ boxes_base,
              float* __restrict__ out)
{
    __shared__ int s_jl[QQ];
    __shared__ int s_cnt;

    int b = blockIdx.y;
    int r0 = blockIdx.x * RCH;
    int nrows = min(RCH, QQ - r0);
    int tid = threadIdx.x;

    if (tid == 0) s_cnt = 0;
    __syncthreads();

    for (int j = tid; j < QQ; j += 128) {
        int lk = __ldg(&g_lk[b * QQ + j]);
        if (lk >= 0) {
            int p = atomicAdd(&s_cnt, 1);
            s_jl[p] = j | (lk << 16);
        }
    }
    __syncthreads();
    int nb = s_cnt;
    if (nb == 0 || tid >= nrows) return;

    int r = r0 + tid;
    int rowi = b * QQ + r;
    float4 pb = __ldg(&pred_boxes[rowi]);
    float hw = 0.5f * pb.z, hh = 0.5f * pb.w;
    float ix0 = pb.x - hw, iy0 = pb.y - hh;
    float ix1 = pb.x + hw, iy1 = pb.y + hh;
    float ia  = (ix1 - ix0) * (iy1 - iy0);
    const float* lrow = pred_logits + (size_t)rowi * CCLS;
    float* orow = out + (size_t)rowi * QQ;

    for (int s = 0; s < nb; s++) {
        int jl = s_jl[s];               // LDS broadcast
        int j = jl & 0xFFFF;
        int lab = jl >> 16;
        float4 jb = __ldg(&boxes_base[b * QQ + j]);   // broadcast, L1-hot

        float l1 = fabsf(pb.x - jb.x) + fabsf(pb.y - jb.y)
                 + fabsf(pb.z - jb.z) + fabsf(pb.w - jb.w);

        float jhw = 0.5f * jb.z, jhh = 0.5f * jb.w;
        float jx0 = jb.x - jhw, jy0 = jb.y - jhh;
        float jx1 = jb.x + jhw, jy1 = jb.y + jhh;
        float ja  = (jx1 - jx0) * (jy1 - jy0);

        float lx = fmaxf(ix0, jx0), ly = fmaxf(iy0, jy0);
        float rx = fminf(ix1, jx1), ry = fminf(iy1, jy1);
        float w = fmaxf(rx - lx, 0.0f);
        float h = fmaxf(ry - ly, 0.0f);
        float inter = w * h;
        float uni = ia + ja - inter;

        float clx = fminf(ix0, jx0), cly = fminf(iy0, jy0);
        float crx = fmaxf(ix1, jx1), cry = fmaxf(iy1, jy1);
        float ac = (crx - clx) * (cry - cly);

        float giou = __fdividef(inter, uni) - __fdividef(ac - uni, ac);

        float x = __ldg(lrow + lab);
        float e = __expf(-x);
        float p = __fdividef(1.0f, 1.0f + e);
        float omp = 1.0f - p;
        float cls = 0.25f * omp * omp * (-__logf(p + 1e-8f))
                  - 0.75f * p * p * (-__logf(omp + 1e-8f));

        orow[j] = 5.0f * l1 + 2.0f * cls - 2.0f * giou;
    }
}

extern "C" void kernel_launch(void* const* d_in, const int* in_sizes, int n_in,
                              void* d_out, int out_size)
{
    const float*  pred_logits      = (const float*)d_in[0];
    const float4* pred_boxes       = (const float4*)d_in[1];
    const float*  pred_logits_base = (const float*)d_in[2];
    const float4* pred_boxes_base  = (const float4*)d_in[3];
    const float4* targets_boxes    = (const float4*)d_in[4];
    float* out = (float*)d_out;

    const long long c_elems = (long long)BB * QQ * QQ;
    int write_mask = (out_size >= c_elems + BB * QQ) ? 1 : 0;

    pseudo_fill_kernel<<<PBLK, 256>>>(
        pred_logits_base, pred_boxes_base, targets_boxes,
        out, out + c_elems, write_mask);

    sparse_kernel<<<dim3(NCH, BB), 128>>>(
        pred_boxes, pred_logits, pred_boxes_base, out);
}

// round 7
// speedup vs baseline: 2.0943x; 2.0943x over previous
#include <cuda_runtime.h>
#include <cstdint>

#define BB 32
#define QQ 900
#define CCLS 91
#define TT 30
#define BIGV 1e9f
#define RT 32                 // rows per block
#define NW 29                 // warps per block (29*32 = 928 >= 900 columns)
#define THR (NW * 32)
#define RTILES ((QQ + RT - 1) / RT)   // 29

// per-row packed pseudo info: keep ? label : -1
__device__ int g_lk[BB * QQ];

// ---------------------------------------------------------------------------
// Kernel 1: warp-per-row pseudo labels + mask.
// Mask GIoU path uses exact IEEE op order (__f*_rn, no FMA contraction):
// a mask flip swaps ~O(10) values for 1e9 across a whole output column.
// ---------------------------------------------------------------------------
__global__ void __launch_bounds__(256)
pseudo_kernel(const float* __restrict__ logits_base,
              const float4* __restrict__ boxes_base,
              const float4* __restrict__ targets,
              float* __restrict__ out_mask, int write_mask)
{
    int warp = (blockIdx.x * blockDim.x + threadIdx.x) >> 5;
    int lane = threadIdx.x & 31;
    if (warp >= BB * QQ) return;
    int b = warp / QQ;

    // warp argmax over 91 logits (first-occurrence tie-break)
    const float* row = logits_base + (size_t)warp * CCLS;
    float best = -3.4e38f;
    int bi = 0;
    for (int c = lane; c < CCLS; c += 32) {
        float x = row[c];
        if (x > best) { best = x; bi = c; }
    }
#pragma unroll
    for (int off = 16; off > 0; off >>= 1) {
        float ov = __shfl_down_sync(0xFFFFFFFFu, best, off);
        int   oi = __shfl_down_sync(0xFFFFFFFFu, bi, off);
        if (ov > best || (ov == best && oi < bi)) { best = ov; bi = oi; }
    }
    best = __shfl_sync(0xFFFFFFFFu, best, 0);
    bi   = __shfl_sync(0xFFFFFFFFu, bi, 0);
    int keep = (best > 0.0f);                 // sigmoid(best) > 0.5

    float4 bb = boxes_base[warp];
    float bx0 = __fsub_rn(bb.x, __fmul_rn(0.5f, bb.z));
    float by0 = __fsub_rn(bb.y, __fmul_rn(0.5f, bb.w));
    float bx1 = __fadd_rn(bb.x, __fmul_rn(0.5f, bb.z));
    float by1 = __fadd_rn(bb.y, __fmul_rn(0.5f, bb.w));
    float barea = __fmul_rn(__fsub_rn(bx1, bx0), __fsub_rn(by1, by0));

    int bad = 0;
    if (lane < TT) {
        float4 tb = targets[b * TT + lane];
        float tx0 = __fsub_rn(tb.x, __fmul_rn(0.5f, tb.z));
        float ty0 = __fsub_rn(tb.y, __fmul_rn(0.5f, tb.w));
        float tx1 = __fadd_rn(tb.x, __fmul_rn(0.5f, tb.z));
        float ty1 = __fadd_rn(tb.y, __fmul_rn(0.5f, tb.w));
        float tarea = __fmul_rn(__fsub_rn(tx1, tx0), __fsub_rn(ty1, ty0));

        float lx = fmaxf(bx0, tx0), ly = fmaxf(by0, ty0);
        float rx = fminf(bx1, tx1), ry = fminf(by1, ty1);
        float w = fmaxf(__fsub_rn(rx, lx), 0.0f);
        float h = fmaxf(__fsub_rn(ry, ly), 0.0f);
        float inter = __fmul_rn(w, h);
        float uni = __fsub_rn(__fadd_rn(barea, tarea), inter);
        float iou = __fdiv_rn(inter, uni);

        float clx = fminf(bx0, tx0), cly = fminf(by0, ty0);
        float crx = fmaxf(bx1, tx1), cry = fmaxf(by1, ty1);
        float cw = fmaxf(__fsub_rn(crx, clx), 0.0f);
        float ch = fmaxf(__fsub_rn(cry, cly), 0.0f);
        float ac = __fmul_rn(cw, ch);
        float g = __fsub_rn(iou, __fdiv_rn(__fsub_rn(ac, uni), ac));
        bad = !(-g > -0.1f);
    }
    keep = keep && (__ballot_sync(0xFFFFFFFFu, bad) == 0u);

    if (lane == 0) {
        g_lk[warp] = keep ? bi : -1;
        if (write_mask) out_mask[warp] = keep ? 1.0f : 0.0f;
    }
}

// ---------------------------------------------------------------------------
// Kernel 2: dense adaptive. Block = (batch b, 32-row tile). Lane owns column
// j for the whole block (j-box in registers). Warp ballots liveness of its
// 32 columns once; inner 32-row loop does full compute or BIG-only stores.
// Coalesced STG.32 directly to the (L2-resident) output. No staging/TMA.
// ---------------------------------------------------------------------------
__global__ void __launch_bounds__(THR)
dense_kernel(const float4* __restrict__ pred_boxes,
             const float*  __restrict__ pred_logits,
             const float4* __restrict__ boxes_base,
             float* __restrict__ out)
{
    __shared__ float  s_cls[RT][CCLS];   // focal class-cost LUT
    __shared__ float4 s_rb[RT];          // row box cxcywh
    __shared__ float4 s_rx[RT];          // row box xyxy
    __shared__ float  s_ra[RT];          // row box area

    int b  = blockIdx.y;
    int r0 = blockIdx.x * RT;
    int nr = min(RT, QQ - r0);
    int tid = threadIdx.x;

    if (tid < nr) {
        float4 pb = __ldg(&pred_boxes[b * QQ + r0 + tid]);
        float hw = 0.5f * pb.z, hh = 0.5f * pb.w;
        float x0 = pb.x - hw, y0 = pb.y - hh;
        float x1 = pb.x + hw, y1 = pb.y + hh;
        s_rb[tid] = pb;
        s_rx[tid] = make_float4(x0, y0, x1, y1);
        s_ra[tid] = (x1 - x0) * (y1 - y0);
    }

    // focal class-cost LUT (fast math; warp-level MUFU cost is negligible)
    for (int idx = tid; idx < nr * CCLS; idx += THR) {
        int r = idx / CCLS, c = idx - r * CCLS;
        float x = __ldg(&pred_logits[(size_t)(b * QQ + r0 + r) * CCLS + c]);
        float e = __expf(-x);
        float p = __fdividef(1.0f, 1.0f + e);
        float omp = 1.0f - p;
        s_cls[r][c] = 0.25f * omp * omp * (-__logf(p + 1e-8f))
                    - 0.75f * p * p * (-__logf(omp + 1e-8f));
    }

    // lane-owned column j
    int j = tid;                       // warp w, lane l -> j = 32w + l
    int valid = (j < QQ);
    int lk = valid ? __ldg(&g_lk[b * QQ + j]) : -1;
    int lab = lk < 0 ? 0 : lk;
    int deadj = (lk < 0);

    float4 jb = valid ? __ldg(&boxes_base[b * QQ + j])
                      : make_float4(0.5f, 0.5f, 0.1f, 0.1f);
    float jhw = 0.5f * jb.z, jhh = 0.5f * jb.w;
    float jx0 = jb.x - jhw, jy0 = jb.y - jhh;
    float jx1 = jb.x + jhw, jy1 = jb.y + jhh;
    float ja  = (jx1 - jx0) * (jy1 - jy0);

    unsigned alive = __ballot_sync(0xFFFFFFFFu, !deadj && valid);

    __syncthreads();

    float* ob = out + ((size_t)b * QQ + r0) * QQ + j;

    if (alive) {
#pragma unroll 2
        for (int r = 0; r < nr; r++) {
            float4 rb = s_rb[r];
            float4 rx = s_rx[r];
            float ra = s_ra[r];

            float l1 = fabsf(rb.x - jb.x) + fabsf(rb.y - jb.y)
                     + fabsf(rb.z - jb.z) + fabsf(rb.w - jb.w);

            float wraw = fminf(rx.z, jx1) - fmaxf(rx.x, jx0);
            float hraw = fminf(rx.w, jy1) - fmaxf(rx.y, jy0);
            float w = fmaxf(wraw, 0.0f);
            float h = fmaxf(hraw, 0.0f);
            float inter = w * h;
            float uni = ra + ja - inter;

            // enclosing box via min+max identity: cw = w_i + w_j - wraw
            float cw = rb.z + jb.z - wraw;
            float ch = rb.w + jb.w - hraw;
            float ac = cw * ch;

            // giou = inter/uni - (ac-uni)/ac  ==  (inter*ac + uni^2 - uni*ac)/(uni*ac)
            float num = fmaf(inter - uni, ac, uni * uni);
            float giou = __fdividef(num, uni * ac);

            float cost = fmaf(2.0f, s_cls[r][lab],
                              fmaf(5.0f, l1, -2.0f * giou));
            float val = deadj ? BIGV : cost;
            if (valid) ob[(size_t)r * QQ] = val;
        }
    } else {
#pragma unroll 4
        for (int r = 0; r < nr; r++)
            if (valid) ob[(size_t)r * QQ] = BIGV;
    }
}

extern "C" void kernel_launch(void* const* d_in, const int* in_sizes, int n_in,
                              void* d_out, int out_size)
{
    const float*  pred_logits      = (const float*)d_in[0];
    const float4* pred_boxes       = (const float4*)d_in[1];
    const float*  pred_logits_base = (const float*)d_in[2];
    const float4* pred_boxes_base  = (const float4*)d_in[3];
    const float4* targets_boxes    = (const float4*)d_in[4];
    float* out = (float*)d_out;

    const long long c_elems = (long long)BB * QQ * QQ;
    int write_mask = (out_size >= c_elems + BB * QQ) ? 1 : 0;

    pseudo_kernel<<<(BB * QQ) / 8, 256>>>(
        pred_logits_base, pred_boxes_base, targets_boxes,
        out + c_elems, write_mask);

    dense_kernel<<<dim3(RTILES, BB), THR>>>(
        pred_boxes, pred_logits, pred_boxes_base, out);
}

// round 8
// speedup vs baseline: 2.3420x; 1.1183x over previous
#include <cuda_runtime.h>
#include <cstdint>

#define BB 32
#define QQ 900
#define CCLS 91
#define TT 30
#define BIGV 1e9f
#define PBLK ((BB * QQ) / 8)          // 3600 blocks in pseudo+fill
#define F4_PER_BLK 1800               // 3600*1800 float4 = BB*QQ*QQ floats
#define RT 32                         // rows per alive-block
#define NW 29
#define THR (NW * 32)                 // 928
#define RTILES ((QQ + RT - 1) / RT)   // 29

// per-row packed pseudo info: keep ? label : -1
__device__ int g_lk[BB * QQ];

// ---------------------------------------------------------------------------
// Kernel 1: warp-per-row pseudo labels + mask, FUSED with the BIG fill of the
// whole cost matrix (coalesced STG.128; output is L2-resident).
// Mask GIoU path uses exact IEEE op order (__f*_rn, no FMA contraction):
// a mask flip swaps ~O(10) values for 1e9 across a whole output column.
// ---------------------------------------------------------------------------
__global__ void __launch_bounds__(256)
pseudo_fill_kernel(const float* __restrict__ logits_base,
                   const float4* __restrict__ boxes_base,
                   const float4* __restrict__ targets,
                   float* __restrict__ out,
                   float* __restrict__ out_mask, int write_mask)
{
    // BIG fill: this block's contiguous 28.8 KB slice
    {
        float4* o4 = (float4*)out + (size_t)blockIdx.x * F4_PER_BLK;
        const float4 big4 = make_float4(BIGV, BIGV, BIGV, BIGV);
#pragma unroll
        for (int t = threadIdx.x; t < F4_PER_BLK; t += 256)
            o4[t] = big4;
    }

    int warp = (blockIdx.x * blockDim.x + threadIdx.x) >> 5;
    int lane = threadIdx.x & 31;
    int b = warp / QQ;

    // warp argmax over 91 logits (first-occurrence tie-break)
    const float* row = logits_base + (size_t)warp * CCLS;
    float best = -3.4e38f;
    int bi = 0;
    for (int c = lane; c < CCLS; c += 32) {
        float x = row[c];
        if (x > best) { best = x; bi = c; }
    }
#pragma unroll
    for (int off = 16; off > 0; off >>= 1) {
        float ov = __shfl_down_sync(0xFFFFFFFFu, best, off);
        int   oi = __shfl_down_sync(0xFFFFFFFFu, bi, off);
        if (ov > best || (ov == best && oi < bi)) { best = ov; bi = oi; }
    }
    best = __shfl_sync(0xFFFFFFFFu, best, 0);
    bi   = __shfl_sync(0xFFFFFFFFu, bi, 0);
    int keep = (best > 0.0f);                 // sigmoid(best) > 0.5

    float4 bb = boxes_base[warp];
    float bx0 = __fsub_rn(bb.x, __fmul_rn(0.5f, bb.z));
    float by0 = __fsub_rn(bb.y, __fmul_rn(0.5f, bb.w));
    float bx1 = __fadd_rn(bb.x, __fmul_rn(0.5f, bb.z));
    float by1 = __fadd_rn(bb.y, __fmul_rn(0.5f, bb.w));
    float barea = __fmul_rn(__fsub_rn(bx1, bx0), __fsub_rn(by1, by0));

    int bad = 0;
    if (lane < TT) {
        float4 tb = targets[b * TT + lane];
        float tx0 = __fsub_rn(tb.x, __fmul_rn(0.5f, tb.z));
        float ty0 = __fsub_rn(tb.y, __fmul_rn(0.5f, tb.w));
        float tx1 = __fadd_rn(tb.x, __fmul_rn(0.5f, tb.z));
        float ty1 = __fadd_rn(tb.y, __fmul_rn(0.5f, tb.w));
        float tarea = __fmul_rn(__fsub_rn(tx1, tx0), __fsub_rn(ty1, ty0));

        float lx = fmaxf(bx0, tx0), ly = fmaxf(by0, ty0);
        float rx = fminf(bx1, tx1), ry = fminf(by1, ty1);
        float w = fmaxf(__fsub_rn(rx, lx), 0.0f);
        float h = fmaxf(__fsub_rn(ry, ly), 0.0f);
        float inter = __fmul_rn(w, h);
        float uni = __fsub_rn(__fadd_rn(barea, tarea), inter);
        float iou = __fdiv_rn(inter, uni);

        float clx = fminf(bx0, tx0), cly = fminf(by0, ty0);
        float crx = fmaxf(bx1, tx1), cry = fmaxf(by1, ty1);
        float cw = fmaxf(__fsub_rn(crx, clx), 0.0f);
        float ch = fmaxf(__fsub_rn(cry, cly), 0.0f);
        float ac = __fmul_rn(cw, ch);
        float g = __fsub_rn(iou, __fdiv_rn(__fsub_rn(ac, uni), ac));
        bad = !(-g > -0.1f);
    }
    keep = keep && (__ballot_sync(0xFFFFFFFFu, bad) == 0u);

    if (lane == 0) {
        g_lk[warp] = keep ? bi : -1;
        if (write_mask) out_mask[warp] = keep ? 1.0f : 0.0f;
    }
}

// ---------------------------------------------------------------------------
// Kernel 2: alive columns only. Block = (batch b, 32-row tile). Per-block
// parallel compaction of alive columns; thread owns one alive column
// (j-state in registers), inner 32-row loop via SMEM broadcast, scattered
// 4B overwrites of the BIG-prefilled (L2-resident) output.
// ---------------------------------------------------------------------------
__global__ void __launch_bounds__(THR)
alive_kernel(const float4* __restrict__ pred_boxes,
             const float*  __restrict__ pred_logits,
             const float4* __restrict__ boxes_base,
             float* __restrict__ out)
{
    __shared__ float  s_cls[RT][CCLS];
    __shared__ float4 s_rb[RT];
    __shared__ float4 s_rx[RT];
    __shared__ float  s_ra[RT];
    __shared__ int    s_jl[QQ];
    __shared__ int    s_cnt;

    int b  = blockIdx.y;
    int r0 = blockIdx.x * RT;
    int nr = min(RT, QQ - r0);
    int tid = threadIdx.x;

    if (tid == 0) s_cnt = 0;
    if (tid >= 32 && tid - 32 < nr) {
        int r = tid - 32;
        float4 pb = __ldg(&pred_boxes[b * QQ + r0 + r]);
        float hw = 0.5f * pb.z, hh = 0.5f * pb.w;
        float x0 = pb.x - hw, y0 = pb.y - hh;
        float x1 = pb.x + hw, y1 = pb.y + hh;
        s_rb[r] = pb;
        s_rx[r] = make_float4(x0, y0, x1, y1);
        s_ra[r] = (x1 - x0) * (y1 - y0);
    }
    __syncthreads();

    // parallel alive-column compaction (order-free)
    for (int j = tid; j < QQ; j += THR) {
        int lk = __ldg(&g_lk[b * QQ + j]);
        if (lk >= 0) {
            int p = atomicAdd(&s_cnt, 1);
            s_jl[p] = j | (lk << 16);
        }
    }

    // focal class-cost LUT (fast math)
    for (int idx = tid; idx < nr * CCLS; idx += THR) {
        int r = idx / CCLS, c = idx - r * CCLS;
        float x = __ldg(&pred_logits[(size_t)(b * QQ + r0 + r) * CCLS + c]);
        float e = __expf(-x);
        float p = __fdividef(1.0f, 1.0f + e);
        float omp = 1.0f - p;
        s_cls[r][c] = 0.25f * omp * omp * (-__logf(p + 1e-8f))
                    - 0.75f * p * p * (-__logf(omp + 1e-8f));
    }
    __syncthreads();
    int nb = s_cnt;

    if (tid >= nb) return;

    int jl = s_jl[tid];
    int j = jl & 0xFFFF;
    int lab = jl >> 16;
    float4 jb = __ldg(&boxes_base[b * QQ + j]);
    float jhw = 0.5f * jb.z, jhh = 0.5f * jb.w;
    float jx0 = jb.x - jhw, jy0 = jb.y - jhh;
    float jx1 = jb.x + jhw, jy1 = jb.y + jhh;
    float ja  = (jx1 - jx0) * (jy1 - jy0);

    float* ob = out + ((size_t)b * QQ + r0) * QQ + j;

#pragma unroll 2
    for (int r = 0; r < nr; r++) {
        float4 rb = s_rb[r];
        float4 rx = s_rx[r];
        float ra = s_ra[r];

        float l1 = fabsf(rb.x - jb.x) + fabsf(rb.y - jb.y)
                 + fabsf(rb.z - jb.z) + fabsf(rb.w - jb.w);

        float wraw = fminf(rx.z, jx1) - fmaxf(rx.x, jx0);
        float hraw = fminf(rx.w, jy1) - fmaxf(rx.y, jy0);
        float w = fmaxf(wraw, 0.0f);
        float h = fmaxf(hraw, 0.0f);
        float inter = w * h;
        float uni = ra + ja - inter;

        // enclosing box via min+max identity: cw = w_i + w_j - wraw
        float cw = rb.z + jb.z - wraw;
        float ch = rb.w + jb.w - hraw;
        float ac = cw * ch;

        // giou = inter/uni - (ac-uni)/ac = (inter*ac + uni^2 - uni*ac)/(uni*ac)
        float num = fmaf(inter - uni, ac, uni * uni);
        float giou = __fdividef(num, uni * ac);

        ob[(size_t)r * QQ] = fmaf(2.0f, s_cls[r][lab],
                                  fmaf(5.0f, l1, -2.0f * giou));
    }
}

extern "C" void kernel_launch(void* const* d_in, const int* in_sizes, int n_in,
                              void* d_out, int out_size)
{
    const float*  pred_logits      = (const float*)d_in[0];
    const float4* pred_boxes       = (const float4*)d_in[1];
    const float*  pred_logits_base = (const float*)d_in[2];
    const float4* pred_boxes_base  = (const float4*)d_in[3];
    const float4* targets_boxes    = (const float4*)d_in[4];
    float* out = (float*)d_out;

    const long long c_elems = (long long)BB * QQ * QQ;
    int write_mask = (out_size >= c_elems + BB * QQ) ? 1 : 0;

    pseudo_fill_kernel<<<PBLK, 256>>>(
        pred_logits_base, pred_boxes_base, targets_boxes,
        out, out + c_elems, write_mask);

    alive_kernel<<<dim3(RTILES, BB), THR>>>(
        pred_boxes, pred_logits, pred_boxes_base, out);
}

// round 9
// speedup vs baseline: 2.3976x; 1.0237x over previous
#include <cuda_runtime.h>
#include <cstdint>

#define BB 32
#define QQ 900
#define CCLS 91
#define TT 30
#define BIGV 1e9f
#define RT 32                          // rows per cost-block
#define THR 928                        // 29 warps
#define RTILES ((QQ + RT - 1) / RT)    // 29

// per-row packed pseudo info: keep ? label : -1
__device__ int g_lk[BB * QQ];

// ---------------------------------------------------------------------------
// Kernel 1: warp-per-row pseudo labels + mask.
// Mask GIoU path uses exact IEEE op order (__f*_rn, no FMA contraction):
// a mask flip swaps ~O(10) values for 1e9 across a whole output column.
// ---------------------------------------------------------------------------
__global__ void __launch_bounds__(256)
pseudo_kernel(const float* __restrict__ logits_base,
              const float4* __restrict__ boxes_base,
              const float4* __restrict__ targets,
              float* __restrict__ out_mask, int write_mask)
{
    int warp = (blockIdx.x * blockDim.x + threadIdx.x) >> 5;
    int lane = threadIdx.x & 31;
    if (warp >= BB * QQ) return;
    int b = warp / QQ;

    // warp argmax over 91 logits (first-occurrence tie-break)
    const float* row = logits_base + (size_t)warp * CCLS;
    float best = -3.4e38f;
    int bi = 0;
    for (int c = lane; c < CCLS; c += 32) {
        float x = row[c];
        if (x > best) { best = x; bi = c; }
    }
#pragma unroll
    for (int off = 16; off > 0; off >>= 1) {
        float ov = __shfl_down_sync(0xFFFFFFFFu, best, off);
        int   oi = __shfl_down_sync(0xFFFFFFFFu, bi, off);
        if (ov > best || (ov == best && oi < bi)) { best = ov; bi = oi; }
    }
    best = __shfl_sync(0xFFFFFFFFu, best, 0);
    bi   = __shfl_sync(0xFFFFFFFFu, bi, 0);
    int keep = (best > 0.0f);                 // sigmoid(best) > 0.5

    float4 bb = boxes_base[warp];
    float bx0 = __fsub_rn(bb.x, __fmul_rn(0.5f, bb.z));
    float by0 = __fsub_rn(bb.y, __fmul_rn(0.5f, bb.w));
    float bx1 = __fadd_rn(bb.x, __fmul_rn(0.5f, bb.z));
    float by1 = __fadd_rn(bb.y, __fmul_rn(0.5f, bb.w));
    float barea = __fmul_rn(__fsub_rn(bx1, bx0), __fsub_rn(by1, by0));

    int bad = 0;
    if (lane < TT) {
        float4 tb = targets[b * TT + lane];
        float tx0 = __fsub_rn(tb.x, __fmul_rn(0.5f, tb.z));
        float ty0 = __fsub_rn(tb.y, __fmul_rn(0.5f, tb.w));
        float tx1 = __fadd_rn(tb.x, __fmul_rn(0.5f, tb.z));
        float ty1 = __fadd_rn(tb.y, __fmul_rn(0.5f, tb.w));
        float tarea = __fmul_rn(__fsub_rn(tx1, tx0), __fsub_rn(ty1, ty0));

        float lx = fmaxf(bx0, tx0), ly = fmaxf(by0, ty0);
        float rx = fminf(bx1, tx1), ry = fminf(by1, ty1);
        float w = fmaxf(__fsub_rn(rx, lx), 0.0f);
        float h = fmaxf(__fsub_rn(ry, ly), 0.0f);
        float inter = __fmul_rn(w, h);
        float uni = __fsub_rn(__fadd_rn(barea, tarea), inter);
        float iou = __fdiv_rn(inter, uni);

        float clx = fminf(bx0, tx0), cly = fminf(by0, ty0);
        float crx = fmaxf(bx1, tx1), cry = fmaxf(by1, ty1);
        float cw = fmaxf(__fsub_rn(crx, clx), 0.0f);
        float ch = fmaxf(__fsub_rn(cry, cly), 0.0f);
        float ac = __fmul_rn(cw, ch);
        float g = __fsub_rn(iou, __fdiv_rn(__fsub_rn(ac, uni), ac));
        bad = !(-g > -0.1f);
    }
    keep = keep && (__ballot_sync(0xFFFFFFFFu, bad) == 0u);

    if (lane == 0) {
        g_lk[warp] = keep ? bi : -1;
        if (write_mask) out_mask[warp] = keep ? 1.0f : 0.0f;
    }
}

// ---------------------------------------------------------------------------
// Kernel 2: single-pass cost matrix. Block = (batch b, 32-row tile).
// Compaction splits columns: alive list at the front of s_jl, dead list at
// the back. Threads < nb own an alive column (register j-state, SMEM row
// broadcast, ~35 ops/entry); threads in [nb,900) own a dead column and
// store BIG. Every output element written exactly once -> no double DRAM.
// ---------------------------------------------------------------------------
__global__ void __launch_bounds__(THR)
cost_kernel(const float4* __restrict__ pred_boxes,
            const float*  __restrict__ pred_logits,
            const float4* __restrict__ boxes_base,
            float* __restrict__ out)
{
    __shared__ float  s_cls[RT][CCLS];
    __shared__ float4 s_rb[RT];
    __shared__ float4 s_rx[RT];
    __shared__ float  s_ra[RT];
    __shared__ int    s_jl[QQ];      // [0,nb): j|lab<<16 ; [nb,900): dead j
    __shared__ int    s_cnt, s_dcnt;

    int b  = blockIdx.y;
    int r0 = blockIdx.x * RT;
    int nr = min(RT, QQ - r0);
    int tid = threadIdx.x;

    if (tid == 0) { s_cnt = 0; s_dcnt = 0; }
    if (tid >= 32 && tid - 32 < nr) {
        int r = tid - 32;
        float4 pb = __ldg(&pred_boxes[b * QQ + r0 + r]);
        float hw = 0.5f * pb.z, hh = 0.5f * pb.w;
        float x0 = pb.x - hw, y0 = pb.y - hh;
        float x1 = pb.x + hw, y1 = pb.y + hh;
        s_rb[r] = pb;
        s_rx[r] = make_float4(x0, y0, x1, y1);
        s_ra[r] = (x1 - x0) * (y1 - y0);
    }
    __syncthreads();

    // split compaction: alive -> front, dead -> back (order-free)
    for (int j = tid; j < QQ; j += THR) {
        int lk = __ldg(&g_lk[b * QQ + j]);
        if (lk >= 0) {
            int p = atomicAdd(&s_cnt, 1);
            s_jl[p] = j | (lk << 16);
        } else {
            int p = atomicAdd(&s_dcnt, 1);
            s_jl[QQ - 1 - p] = j;
        }
    }

    // focal class-cost LUT (fast math)
    for (int idx = tid; idx < nr * CCLS; idx += THR) {
        int r = idx / CCLS, c = idx - r * CCLS;
        float x = __ldg(&pred_logits[(size_t)(b * QQ + r0 + r) * CCLS + c]);
        float e = __expf(-x);
        float p = __fdividef(1.0f, 1.0f + e);
        float omp = 1.0f - p;
        s_cls[r][c] = 0.25f * omp * omp * (-__logf(p + 1e-8f))
                    - 0.75f * p * p * (-__logf(omp + 1e-8f));
    }
    __syncthreads();
    int nb = s_cnt;

    if (tid < nb) {
        // ---- alive column: full cost ----
        int jl = s_jl[tid];
        int j = jl & 0xFFFF;
        int lab = jl >> 16;
        float4 jb = __ldg(&boxes_base[b * QQ + j]);
        float jhw = 0.5f * jb.z, jhh = 0.5f * jb.w;
        float jx0 = jb.x - jhw, jy0 = jb.y - jhh;
        float jx1 = jb.x + jhw, jy1 = jb.y + jhh;
        float ja  = (jx1 - jx0) * (jy1 - jy0);

        float* ob = out + ((size_t)b * QQ + r0) * QQ + j;

#pragma unroll 2
        for (int r = 0; r < nr; r++) {
            float4 rb = s_rb[r];
            float4 rx = s_rx[r];
            float ra = s_ra[r];

            float l1 = fabsf(rb.x - jb.x) + fabsf(rb.y - jb.y)
                     + fabsf(rb.z - jb.z) + fabsf(rb.w - jb.w);

            float wraw = fminf(rx.z, jx1) - fmaxf(rx.x, jx0);
            float hraw = fminf(rx.w, jy1) - fmaxf(rx.y, jy0);
            float w = fmaxf(wraw, 0.0f);
            float h = fmaxf(hraw, 0.0f);
            float inter = w * h;
            float uni = ra + ja - inter;

            // enclosing box via min+max identity
            float cw = rb.z + jb.z - wraw;
            float ch = rb.w + jb.w - hraw;
            float ac = cw * ch;

            // giou = inter/uni - (ac-uni)/ac = (inter*ac + uni^2 - uni*ac)/(uni*ac)
            float num = fmaf(inter - uni, ac, uni * uni);
            float giou = __fdividef(num, uni * ac);

            ob[(size_t)r * QQ] = fmaf(2.0f, s_cls[r][lab],
                                      fmaf(5.0f, l1, -2.0f * giou));
        }
    } else if (tid < QQ) {
        // ---- dead column: BIG fill ----
        int j = s_jl[tid];
        float* ob = out + ((size_t)b * QQ + r0) * QQ + j;
#pragma unroll 4
        for (int r = 0; r < nr; r++)
            ob[(size_t)r * QQ] = BIGV;
    }
}

extern "C" void kernel_launch(void* const* d_in, const int* in_sizes, int n_in,
                              void* d_out, int out_size)
{
    const float*  pred_logits      = (const float*)d_in[0];
    const float4* pred_boxes       = (const float4*)d_in[1];
    const float*  pred_logits_base = (const float*)d_in[2];
    const float4* pred_boxes_base  = (const float4*)d_in[3];
    const float4* targets_boxes    = (const float4*)d_in[4];
    float* out = (float*)d_out;

    const long long c_elems = (long long)BB * QQ * QQ;
    int write_mask = (out_size >= c_elems + BB * QQ) ? 1 : 0;

    pseudo_kernel<<<(BB * QQ) / 8, 256>>>(
        pred_logits_base, pred_boxes_base, targets_boxes,
        out + c_elems, write_mask);

    cost_kernel<<<dim3(RTILES, BB), THR>>>(
        pred_boxes, pred_logits, pred_boxes_base, out);
}

// round 11
// speedup vs baseline: 2.8635x; 1.1943x over previous
#include <cuda_runtime.h>
#include <cstdint>

#define BB 32
#define QQ 900
#define CCLS 91
#define TT 30
#define BIGV 1e9f
#define RT 16                          // rows per cost-block
#define THR 512
#define RTILES ((QQ + RT - 1) / RT)    // 57

// dynamic SMEM layout (floats):
//  srow   : RT*QQ            (14400)  tile
//  s_cls  : RT*CCLS          (1456)   focal LUT
//  s_rb   : RT*4             row box cxcywh
//  s_rx   : RT*4             row box xyxy
//  s_ra   : RT               row area
//  s_jl   : QQ (as int)      alive list
//  s_cnt  : 1 (as int)
#define SM_SROW   0
#define SM_CLS    (SM_SROW + RT * QQ)
#define SM_RB     (SM_CLS + RT * CCLS)
#define SM_RX     (SM_RB + RT * 4)
#define SM_RA     (SM_RX + RT * 4)
#define SM_JL     (SM_RA + RT)
#define SM_CNT    (SM_JL + QQ)
#define SM_TOTALF (SM_CNT + 4)
#define SMEM_BYTES (SM_TOTALF * 4)

// per-row packed pseudo info: keep ? label : -1
__device__ int g_lk[BB * QQ];

// ---------------------------------------------------------------------------
// Kernel 1: warp-per-row pseudo labels + mask.
// Mask GIoU path uses exact IEEE op order (__f*_rn, no FMA contraction):
// a mask flip swaps ~O(10) values for 1e9 across a whole output column.
// ---------------------------------------------------------------------------
__global__ void __launch_bounds__(256)
pseudo_kernel(const float* __restrict__ logits_base,
              const float4* __restrict__ boxes_base,
              const float4* __restrict__ targets,
              float* __restrict__ out_mask, int write_mask)
{
    int warp = (blockIdx.x * blockDim.x + threadIdx.x) >> 5;
    int lane = threadIdx.x & 31;
    if (warp >= BB * QQ) return;
    int b = warp / QQ;

    // warp argmax over 91 logits (first-occurrence tie-break)
    const float* row = logits_base + (size_t)warp * CCLS;
    float best = -3.4e38f;
    int bi = 0;
    for (int c = lane; c < CCLS; c += 32) {
        float x = row[c];
        if (x > best) { best = x; bi = c; }
    }
#pragma unroll
    for (int off = 16; off > 0; off >>= 1) {
        float ov = __shfl_down_sync(0xFFFFFFFFu, best, off);
        int   oi = __shfl_down_sync(0xFFFFFFFFu, bi, off);
        if (ov > best || (ov == best && oi < bi)) { best = ov; bi = oi; }
    }
    best = __shfl_sync(0xFFFFFFFFu, best, 0);
    bi   = __shfl_sync(0xFFFFFFFFu, bi, 0);
    int keep = (best > 0.0f);                 // sigmoid(best) > 0.5

    float4 bb = boxes_base[warp];
    float bx0 = __fsub_rn(bb.x, __fmul_rn(0.5f, bb.z));
    float by0 = __fsub_rn(bb.y, __fmul_rn(0.5f, bb.w));
    float bx1 = __fadd_rn(bb.x, __fmul_rn(0.5f, bb.z));
    float by1 = __fadd_rn(bb.y, __fmul_rn(0.5f, bb.w));
    float barea = __fmul_rn(__fsub_rn(bx1, bx0), __fsub_rn(by1, by0));

    int bad = 0;
    if (lane < TT) {
        float4 tb = targets[b * TT + lane];
        float tx0 = __fsub_rn(tb.x, __fmul_rn(0.5f, tb.z));
        float ty0 = __fsub_rn(tb.y, __fmul_rn(0.5f, tb.w));
        float tx1 = __fadd_rn(tb.x, __fmul_rn(0.5f, tb.z));
        float ty1 = __fadd_rn(tb.y, __fmul_rn(0.5f, tb.w));
        float tarea = __fmul_rn(__fsub_rn(tx1, tx0), __fsub_rn(ty1, ty0));

        float lx = fmaxf(bx0, tx0), ly = fmaxf(by0, ty0);
        float rx = fminf(bx1, tx1), ry = fminf(by1, ty1);
        float w = fmaxf(__fsub_rn(rx, lx), 0.0f);
        float h = fmaxf(__fsub_rn(ry, ly), 0.0f);
        float inter = __fmul_rn(w, h);
        float uni = __fsub_rn(__fadd_rn(barea, tarea), inter);
        float iou = __fdiv_rn(inter, uni);

        float clx = fminf(bx0, tx0), cly = fminf(by0, ty0);
        float crx = fmaxf(bx1, tx1), cry = fmaxf(by1, ty1);
        float cw = fmaxf(__fsub_rn(crx, clx), 0.0f);
        float ch = fmaxf(__fsub_rn(cry, cly), 0.0f);
        float ac = __fmul_rn(cw, ch);
        float g = __fsub_rn(iou, __fdiv_rn(__fsub_rn(ac, uni), ac));
        bad = !(-g > -0.1f);
    }
    keep = keep && (__ballot_sync(0xFFFFFFFFu, bad) == 0u);

    if (lane == 0) {
        g_lk[warp] = keep ? bi : -1;
        if (write_mask) out_mask[warp] = keep ? 1.0f : 0.0f;
    }
}

// ---------------------------------------------------------------------------
// Kernel 2: single-pass cost via SMEM staging (dynamic SMEM, ~68KB,
// 3 blocks/SM). BIG-fill tile, alive-only compaction, thread-owns-alive-
// column scatter into SMEM, flat float4 coalesced writeout. Every output
// element written to GMEM exactly once, fully coalesced.
// ---------------------------------------------------------------------------
__global__ void __launch_bounds__(THR)
cost_kernel(const float4* __restrict__ pred_boxes,
            const float*  __restrict__ pred_logits,
            const float4* __restrict__ boxes_base,
            float* __restrict__ out)
{
    extern __shared__ __align__(16) float sm[];
    float*  srow  = sm + SM_SROW;            // [RT][QQ]
    float*  s_cls = sm + SM_CLS;             // [RT][CCLS]
    float4* s_rb  = (float4*)(sm + SM_RB);   // [RT]
    float4* s_rx  = (float4*)(sm + SM_RX);   // [RT]
    float*  s_ra  = sm + SM_RA;              // [RT]
    int*    s_jl  = (int*)(sm + SM_JL);      // [QQ]
    int*    s_cnt = (int*)(sm + SM_CNT);

    int b  = blockIdx.y;
    int r0 = blockIdx.x * RT;
    int nr = min(RT, QQ - r0);
    int tid = threadIdx.x;

    if (tid == 0) s_cnt[0] = 0;
    if (tid >= 32 && tid - 32 < nr) {
        int r = tid - 32;
        float4 pb = __ldg(&pred_boxes[b * QQ + r0 + r]);
        float hw = 0.5f * pb.z, hh = 0.5f * pb.w;
        float x0 = pb.x - hw, y0 = pb.y - hh;
        float x1 = pb.x + hw, y1 = pb.y + hh;
        s_rb[r] = pb;
        s_rx[r] = make_float4(x0, y0, x1, y1);
        s_ra[r] = (x1 - x0) * (y1 - y0);
    }
    __syncthreads();

    // alive-column compaction (order-free)
    for (int j = tid; j < QQ; j += THR) {
        int lk = __ldg(&g_lk[b * QQ + j]);
        if (lk >= 0) {
            int p = atomicAdd(s_cnt, 1);
            s_jl[p] = j | (lk << 16);
        }
    }

    // focal class-cost LUT (fast math)
    for (int idx = tid; idx < nr * CCLS; idx += THR) {
        int r = idx / CCLS, c = idx - r * CCLS;
        float x = __ldg(&pred_logits[(size_t)(b * QQ + r0 + r) * CCLS + c]);
        float e = __expf(-x);
        float p = __fdividef(1.0f, 1.0f + e);
        float omp = 1.0f - p;
        s_cls[r * CCLS + c] = 0.25f * omp * omp * (-__logf(p + 1e-8f))
                            - 0.75f * p * p * (-__logf(omp + 1e-8f));
    }

    // BIG-fill the SMEM tile (flat float4)
    {
        float4* s4 = (float4*)srow;
        const int n4 = RT * QQ / 4;   // 3600
        const float4 big4 = make_float4(BIGV, BIGV, BIGV, BIGV);
#pragma unroll
        for (int t = tid; t < n4; t += THR)
            s4[t] = big4;
    }
    __syncthreads();
    int nb = s_cnt[0];

    // alive columns: thread owns one column, fills its nr entries
    for (int s = tid; s < nb; s += THR) {
        int jl = s_jl[s];
        int j = jl & 0xFFFF;
        int lab = jl >> 16;
        float4 jb = __ldg(&boxes_base[b * QQ + j]);
        float jhw = 0.5f * jb.z, jhh = 0.5f * jb.w;
        float jx0 = jb.x - jhw, jy0 = jb.y - jhh;
        float jx1 = jb.x + jhw, jy1 = jb.y + jhh;
        float ja  = (jx1 - jx0) * (jy1 - jy0);

#pragma unroll 4
        for (int r = 0; r < nr; r++) {
            float4 rb = s_rb[r];
            float4 rx = s_rx[r];
            float ra = s_ra[r];

            float l1 = fabsf(rb.x - jb.x) + fabsf(rb.y - jb.y)
                     + fabsf(rb.z - jb.z) + fabsf(rb.w - jb.w);

            float wraw = fminf(rx.z, jx1) - fmaxf(rx.x, jx0);
            float hraw = fminf(rx.w, jy1) - fmaxf(rx.y, jy0);
            float w = fmaxf(wraw, 0.0f);
            float h = fmaxf(hraw, 0.0f);
            float inter = w * h;
            float uni = ra + ja - inter;

            // enclosing box via min+max identity: cw = w_i + w_j - wraw
            float cw = rb.z + jb.z - wraw;
            float ch = rb.w + jb.w - hraw;
            float ac = cw * ch;

            // giou = inter/uni - (ac-uni)/ac = (inter*ac + uni^2 - uni*ac)/(uni*ac)
            float num = fmaf(inter - uni, ac, uni * uni);
            float giou = __fdividef(num, uni * ac);

            srow[r * QQ + j] = fmaf(2.0f, s_cls[r * CCLS + lab],
                                    fmaf(5.0f, l1, -2.0f * giou));
        }
    }
    __syncthreads();

    // coalesced writeout: flat float4, row-major
    {
        const float4* s4 = (const float4*)srow;
        const int q4 = QQ / 4;                 // 225
        const int n4 = RT * q4;                // 3600
        size_t base = ((size_t)b * QQ + r0) * QQ;
#pragma unroll
        for (int t = tid; t < n4; t += THR) {
            int r = t / q4, c = t - r * q4;
            if (r < nr)
                *(float4*)(out + base + (size_t)r * QQ + c * 4) = s4[t];
        }
    }
}

extern "C" void kernel_launch(void* const* d_in, const int* in_sizes, int n_in,
                              void* d_out, int out_size)
{
    const float*  pred_logits      = (const float*)d_in[0];
    const float4* pred_boxes       = (const float4*)d_in[1];
    const float*  pred_logits_base = (const float*)d_in[2];
    const float4* pred_boxes_base  = (const float4*)d_in[3];
    const float4* targets_boxes    = (const float4*)d_in[4];
    float* out = (float*)d_out;

    const long long c_elems = (long long)BB * QQ * QQ;
    int write_mask = (out_size >= c_elems + BB * QQ) ? 1 : 0;

    cudaFuncSetAttribute(cost_kernel,
                         cudaFuncAttributeMaxDynamicSharedMemorySize,
                         SMEM_BYTES);

    pseudo_kernel<<<(BB * QQ) / 8, 256>>>(
        pred_logits_base, pred_boxes_base, targets_boxes,
        out + c_elems, write_mask);

    cost_kernel<<<dim3(RTILES, BB), THR, SMEM_BYTES>>>(
        pred_boxes, pred_logits, pred_boxes_base, out);
}